// round 5
// baseline (speedup 1.0000x reference)
#include <cuda_runtime.h>

#define BB 256
#define TT 2048
#define II 128
#define HH 256
#define AA 8

typedef unsigned long long ull;

// 512MB scratch for xproj[b][t][h]
__device__ float g_xproj[(size_t)BB * TT * HH];

__device__ __forceinline__ ull ffma2(ull a, ull b, ull c) {
  ull d;
  asm("fma.rn.f32x2 %0, %1, %2, %3;" : "=l"(d) : "l"(a), "l"(b), "l"(c));
  return d;
}
__device__ __forceinline__ ull pack2(float lo, float hi) {
  ull d;
  asm("mov.b64 %0, {%1, %2};" : "=l"(d) : "f"(lo), "f"(hi));
  return d;
}
__device__ __forceinline__ float hsum2(ull v) {
  float lo, hi;
  asm("mov.b64 {%0, %1}, %2;" : "=f"(lo), "=f"(hi) : "l"(v));
  return lo + hi;
}

// ---------------------------------------------------------------------------
// Kernel 1: xproj[r][j] = sum_k x[r][k] * W_ih[j][k]
// 512 threads: thread = (j = tid&255, kh = tid>>8). Each thread holds its
// k-half of W_ih[j] in 32 ull regs (~105 regs total -> no spill, 16 warps).
// x staged in double-buffered 8-row smem chunks (broadcast LDS.128).
// k-halves reduced via double-buffered smem partials; ONE barrier per chunk.
// ---------------------------------------------------------------------------
__global__ void __launch_bounds__(512) xproj_kernel(
    const float* __restrict__ x, const float* __restrict__ W_ih) {
  __shared__ float sX[2][1024];      // 8 rows x 128 floats, double buffered
  __shared__ float sP[2][8 * 256];   // partials, double buffered

  const int tid = threadIdx.x;
  const int j = tid & 255;
  const int kh = tid >> 8;

  // W regs: k in [kh*64, kh*64+64)
  ull w[32];
  {
    const float2* wp =
        reinterpret_cast<const float2*>(W_ih + j * II + kh * 64);
    #pragma unroll
    for (int i = 0; i < 32; ++i) {
      float2 v = __ldg(wp + i);
      w[i] = pack2(v.x, v.y);
    }
  }

  const size_t rowbase = (size_t)blockIdx.x * 256;
  const float4* xg4 = reinterpret_cast<const float4*>(x + rowbase * II);

  if (tid < 256) {
    reinterpret_cast<float4*>(sX[0])[tid] = __ldg(xg4 + tid);
  }
  __syncthreads();

  for (int c = 0; c < 32; ++c) {
    float4 pf;
    if (c < 31 && tid < 256) pf = __ldg(xg4 + (c + 1) * 256 + tid);

    const float* cur = sX[c & 1];
    ull acc[8];
    #pragma unroll
    for (int r = 0; r < 8; ++r) acc[r] = 0ull;

    #pragma unroll
    for (int r = 0; r < 8; ++r) {
      const ulonglong2* xr =
          reinterpret_cast<const ulonglong2*>(cur + r * II + kh * 64);
      #pragma unroll
      for (int q = 0; q < 16; ++q) {
        ulonglong2 xv = xr[q];
        acc[r] = ffma2(w[2 * q],     xv.x, acc[r]);
        acc[r] = ffma2(w[2 * q + 1], xv.y, acc[r]);
      }
    }

    float p[8];
    #pragma unroll
    for (int r = 0; r < 8; ++r) p[r] = hsum2(acc[r]);

    if (kh == 1) {
      #pragma unroll
      for (int r = 0; r < 8; ++r) sP[c & 1][r * 256 + j] = p[r];
    }
    if (c < 31 && tid < 256) {
      reinterpret_cast<float4*>(sX[(c + 1) & 1])[tid] = pf;
    }
    __syncthreads();
    if (kh == 0) {
      float* op = g_xproj + (rowbase + (size_t)c * 8) * HH + j;
      #pragma unroll
      for (int r = 0; r < 8; ++r) {
        op[r * HH] = p[r] + sP[c & 1][r * 256 + j];
      }
    }
  }
}

// ---------------------------------------------------------------------------
// Kernel 2: recurrence. 128 CTAs x 1024 threads (32 warps, 8/SMSP), one CTA
// per batch pair. Thread (JP = tid&127, KH = tid>>7 in 0..7) computes j in
// {2JP,2JP+1} over k in [32KH, 32KH+32). W per j: 16 floats in regs (8 ull)
// + 16 floats via conflict-free lane-spread LDS.128. h single-buffered in
// smem (broadcast reads), f32x2 FMAs. 8-way k-reduction via float4 smem
// partials; KH==0 finalizes (h_old re-read from smem - no hold regs).
// ---------------------------------------------------------------------------
__global__ void __launch_bounds__(1024, 1) recurrence_kernel(
    const float* __restrict__ hx, const float* __restrict__ W_hh,
    const float* __restrict__ W_actor, const float* __restrict__ W_critic,
    float* __restrict__ out) {
  extern __shared__ float smem[];
  // sW4: [KH(8)][jsel(2)][q(4)][JP(128)] float4 = 8192 float4 = 128KB
  float4* sW4   = reinterpret_cast<float4*>(smem);
  float*  sh0   = smem + 32768;                          // [256]
  float*  sh1   = sh0 + 256;                             // [256]
  float4* spart = reinterpret_cast<float4*>(sh1 + 256);  // [7][128]

  const int tid = threadIdx.x;
  const int JP = tid & 127;
  const int KH = tid >> 7;            // 0..7
  const int j0 = 2 * JP, j1 = j0 + 1;
  const int kb = KH * 32;
  const int b0 = blockIdx.x * 2, b1 = b0 + 1;

  // ---- stage W regs: k in [kb, kb+16) ----
  ull wA[8], wB[8];
  {
    const float2* r0p = reinterpret_cast<const float2*>(W_hh + j0 * HH + kb);
    const float2* r1p = reinterpret_cast<const float2*>(W_hh + j1 * HH + kb);
    #pragma unroll
    for (int i = 0; i < 8; ++i) {
      float2 a = __ldg(r0p + i);
      float2 b = __ldg(r1p + i);
      wA[i] = pack2(a.x, a.y);
      wB[i] = pack2(b.x, b.y);
    }
  }
  // ---- stage W smem: k in [kb+16, kb+32) = 4 float4 per j ----
  #pragma unroll
  for (int q = 0; q < 4; ++q) {
    sW4[((KH * 2 + 0) * 4 + q) * 128 + JP] =
        *reinterpret_cast<const float4*>(W_hh + j0 * HH + kb + 16 + 4 * q);
    sW4[((KH * 2 + 1) * 4 + q) * 128 + JP] =
        *reinterpret_cast<const float4*>(W_hh + j1 * HH + kb + 16 + 4 * q);
  }

  // ---- init h ----
  if (tid < 256) {
    sh0[tid] = hx[b0 * HH + tid];
    sh1[tid] = hx[b1 * HH + tid];
  }
  __syncthreads();

  const float* xb0 = g_xproj + (size_t)b0 * TT * HH + j0;
  const float* xb1 = g_xproj + (size_t)b1 * TT * HH + j0;
  const ulonglong2* hp0 = reinterpret_cast<const ulonglong2*>(sh0 + kb);
  const ulonglong2* hp1 = reinterpret_cast<const ulonglong2*>(sh1 + kb);
  const ulonglong2* sWa =
      reinterpret_cast<const ulonglong2*>(sW4 + (KH * 2 + 0) * 4 * 128);
  const ulonglong2* sWb =
      reinterpret_cast<const ulonglong2*>(sW4 + (KH * 2 + 1) * 4 * 128);

  for (int t = 0; t < TT; ++t) {
    float2 xq0, xq1;
    if (KH == 0) {
      xq0 = __ldg(reinterpret_cast<const float2*>(xb0 + (size_t)t * HH));
      xq1 = __ldg(reinterpret_cast<const float2*>(xb1 + (size_t)t * HH));
    }
    ull acc00 = 0ull, acc10 = 0ull, acc01 = 0ull, acc11 = 0ull;
    // register-W part: k = kb .. kb+15
    #pragma unroll
    for (int q = 0; q < 4; ++q) {
      ulonglong2 v0 = hp0[q];
      ulonglong2 v1 = hp1[q];
      acc00 = ffma2(wA[2 * q],     v0.x, acc00);
      acc10 = ffma2(wB[2 * q],     v0.x, acc10);
      acc01 = ffma2(wA[2 * q],     v1.x, acc01);
      acc11 = ffma2(wB[2 * q],     v1.x, acc11);
      acc00 = ffma2(wA[2 * q + 1], v0.y, acc00);
      acc10 = ffma2(wB[2 * q + 1], v0.y, acc10);
      acc01 = ffma2(wA[2 * q + 1], v1.y, acc01);
      acc11 = ffma2(wB[2 * q + 1], v1.y, acc11);
    }
    // smem-W part: k = kb+16 .. kb+31
    #pragma unroll
    for (int q = 0; q < 4; ++q) {
      ulonglong2 v0 = hp0[4 + q];
      ulonglong2 v1 = hp1[4 + q];
      ulonglong2 wa = sWa[q * 128 + JP];
      ulonglong2 wb = sWb[q * 128 + JP];
      acc00 = ffma2(wa.x, v0.x, acc00);
      acc10 = ffma2(wb.x, v0.x, acc10);
      acc01 = ffma2(wa.x, v1.x, acc01);
      acc11 = ffma2(wb.x, v1.x, acc11);
      acc00 = ffma2(wa.y, v0.y, acc00);
      acc10 = ffma2(wb.y, v0.y, acc10);
      acc01 = ffma2(wa.y, v1.y, acc01);
      acc11 = ffma2(wb.y, v1.y, acc11);
    }

    float p00 = hsum2(acc00);
    float p10 = hsum2(acc10);
    float p01 = hsum2(acc01);
    float p11 = hsum2(acc11);

    if (KH) {
      spart[(KH - 1) * 128 + JP] = make_float4(p00, p10, p01, p11);
    }
    __syncthreads();
    if (KH == 0) {
      #pragma unroll
      for (int g = 0; g < 7; ++g) {
        float4 s = spart[g * 128 + JP];
        p00 += s.x; p10 += s.y; p01 += s.z; p11 += s.w;
      }
      p00 += xq0.x; p10 += xq0.y;
      p01 += xq1.x; p11 += xq1.y;
      float2 ho0 = *reinterpret_cast<const float2*>(sh0 + j0);
      float2 ho1 = *reinterpret_cast<const float2*>(sh1 + j0);
      float2 hn0, hn1;
      hn0.x = 0.8f * ho0.x + 0.2f * fmaxf(p00, 0.0f);
      hn0.y = 0.8f * ho0.y + 0.2f * fmaxf(p10, 0.0f);
      hn1.x = 0.8f * ho1.x + 0.2f * fmaxf(p01, 0.0f);
      hn1.y = 0.8f * ho1.y + 0.2f * fmaxf(p11, 0.0f);
      *reinterpret_cast<float2*>(sh0 + j0) = hn0;
      *reinterpret_cast<float2*>(sh1 + j0) = hn1;
    }
    __syncthreads();
  }

  // -------- epilogue --------
  float* out_actor  = out;                 // [B][A]
  float* out_critic = out + BB * AA;       // [B]
  float* out_hx     = out + BB * AA + BB;  // [B][H]

  if (tid < HH) {
    out_hx[b0 * HH + tid] = sh0[tid];
    out_hx[b1 * HH + tid] = sh1[tid];
  }

  const int wid = tid >> 5, lane = tid & 31;
  if (wid < AA) {
    float pa0 = 0.f, pa1 = 0.f;
    for (int jj = lane; jj < HH; jj += 32) {
      float wa = W_actor[wid * HH + jj];
      pa0 += wa * sh0[jj];
      pa1 += wa * sh1[jj];
    }
    #pragma unroll
    for (int off = 16; off; off >>= 1) {
      pa0 += __shfl_down_sync(0xffffffffu, pa0, off);
      pa1 += __shfl_down_sync(0xffffffffu, pa1, off);
    }
    if (lane == 0) {
      out_actor[b0 * AA + wid] = pa0;
      out_actor[b1 * AA + wid] = pa1;
    }
  }
  if (wid == 8) {
    float pc0 = 0.f, pc1 = 0.f;
    for (int jj = lane; jj < HH; jj += 32) {
      float wc = W_critic[jj];
      pc0 += wc * sh0[jj];
      pc1 += wc * sh1[jj];
    }
    #pragma unroll
    for (int off = 16; off; off >>= 1) {
      pc0 += __shfl_down_sync(0xffffffffu, pc0, off);
      pc1 += __shfl_down_sync(0xffffffffu, pc1, off);
    }
    if (lane == 0) {
      out_critic[b0] = pc0;
      out_critic[b1] = pc1;
    }
  }
}

// ---------------------------------------------------------------------------
extern "C" void kernel_launch(void* const* d_in, const int* in_sizes, int n_in,
                              void* d_out, int out_size) {
  const float* x        = (const float*)d_in[0];
  const float* hx       = (const float*)d_in[1];
  const float* W_ih     = (const float*)d_in[2];
  const float* W_hh     = (const float*)d_in[3];
  const float* W_actor  = (const float*)d_in[4];
  const float* W_critic = (const float*)d_in[5];
  float* out = (float*)d_out;

  // recurrence smem: 32768 (W) + 512 (h) + 7*128*4 (partials) floats
  const int smem2 = (32768 + 512 + 3584) * (int)sizeof(float);  // 147456

  cudaFuncSetAttribute(recurrence_kernel,
                       cudaFuncAttributeMaxDynamicSharedMemorySize, smem2);

  xproj_kernel<<<(BB * TT) / 256, 512>>>(x, W_ih);
  recurrence_kernel<<<BB / 2, 1024, smem2>>>(hx, W_hh, W_actor, W_critic, out);
}

// round 6
// speedup vs baseline: 1.4952x; 1.4952x over previous
#include <cuda_runtime.h>

#define BB 256
#define TT 2048
#define II 128
#define HH 256
#define AA 8

typedef unsigned long long ull;

// 512MB scratch for xproj[b][t][h]
__device__ float g_xproj[(size_t)BB * TT * HH];

__device__ __forceinline__ ull ffma2(ull a, ull b, ull c) {
  ull d;
  asm("fma.rn.f32x2 %0, %1, %2, %3;" : "=l"(d) : "l"(a), "l"(b), "l"(c));
  return d;
}
__device__ __forceinline__ ull add2(ull a, ull b) {
  ull d;
  asm("add.rn.f32x2 %0, %1, %2;" : "=l"(d) : "l"(a), "l"(b));
  return d;
}
__device__ __forceinline__ ull pack2(float lo, float hi) {
  ull d;
  asm("mov.b64 %0, {%1, %2};" : "=l"(d) : "f"(lo), "f"(hi));
  return d;
}
__device__ __forceinline__ float hsum2(ull v) {
  float lo, hi;
  asm("mov.b64 {%0, %1}, %2;" : "=f"(lo), "=f"(hi) : "l"(v));
  return lo + hi;
}

// ---------------------------------------------------------------------------
// Kernel 1: xproj (unchanged from R5: 512 thr, W in regs, 2-way k-split)
// ---------------------------------------------------------------------------
__global__ void __launch_bounds__(512) xproj_kernel(
    const float* __restrict__ x, const float* __restrict__ W_ih) {
  __shared__ float sX[2][1024];
  __shared__ float sP[2][8 * 256];

  const int tid = threadIdx.x;
  const int j = tid & 255;
  const int kh = tid >> 8;

  ull w[32];
  {
    const float2* wp =
        reinterpret_cast<const float2*>(W_ih + j * II + kh * 64);
    #pragma unroll
    for (int i = 0; i < 32; ++i) {
      float2 v = __ldg(wp + i);
      w[i] = pack2(v.x, v.y);
    }
  }

  const size_t rowbase = (size_t)blockIdx.x * 256;
  const float4* xg4 = reinterpret_cast<const float4*>(x + rowbase * II);

  if (tid < 256) {
    reinterpret_cast<float4*>(sX[0])[tid] = __ldg(xg4 + tid);
  }
  __syncthreads();

  for (int c = 0; c < 32; ++c) {
    float4 pf;
    if (c < 31 && tid < 256) pf = __ldg(xg4 + (c + 1) * 256 + tid);

    const float* cur = sX[c & 1];
    ull acc[8];
    #pragma unroll
    for (int r = 0; r < 8; ++r) acc[r] = 0ull;

    #pragma unroll
    for (int r = 0; r < 8; ++r) {
      const ulonglong2* xr =
          reinterpret_cast<const ulonglong2*>(cur + r * II + kh * 64);
      #pragma unroll
      for (int q = 0; q < 16; ++q) {
        ulonglong2 xv = xr[q];
        acc[r] = ffma2(w[2 * q],     xv.x, acc[r]);
        acc[r] = ffma2(w[2 * q + 1], xv.y, acc[r]);
      }
    }

    float p[8];
    #pragma unroll
    for (int r = 0; r < 8; ++r) p[r] = hsum2(acc[r]);

    if (kh == 1) {
      #pragma unroll
      for (int r = 0; r < 8; ++r) sP[c & 1][r * 256 + j] = p[r];
    }
    if (c < 31 && tid < 256) {
      reinterpret_cast<float4*>(sX[(c + 1) & 1])[tid] = pf;
    }
    __syncthreads();
    if (kh == 0) {
      float* op = g_xproj + (rowbase + (size_t)c * 8) * HH + j;
      #pragma unroll
      for (int r = 0; r < 8; ++r) {
        op[r * HH] = p[r] + sP[c & 1][r * 256 + j];
      }
    }
  }
}

// ---------------------------------------------------------------------------
// Kernel 2: recurrence. 128 CTAs x 512 threads, one CTA per batch pair.
// Thread (JQ = tid>>3, KH = tid&7): j in [4JQ, 4JQ+4), k in [32KH, 32KH+32),
// both batch rows. W: 40 ull in regs (q=0..4) + 24 ull via conflict-free
// [e][512] LDS.128 (q=5..7). h double-buffered in smem, padded [8][36] per
// batch (KH lanes hit distinct bank groups). k-reduction = 3-round
// reduce-scatter via shfl_xor(1,2,4) on f32x2 packs; each lane ends owning
// one (j, b), finalizes with reg-resident h_old, prefetched xproj addend.
// ONE barrier per step, no partial-exchange smem.
// ---------------------------------------------------------------------------
__global__ void __launch_bounds__(512, 1) recurrence_kernel(
    const float* __restrict__ hx, const float* __restrict__ W_hh,
    const float* __restrict__ W_actor, const float* __restrict__ W_critic,
    float* __restrict__ out) {
  extern __shared__ float smem[];
  // sW: 12 * 512 ulonglong2 = 98304B, then h buffers [2 parity][2 b][288]
  ulonglong2* sW = reinterpret_cast<ulonglong2*>(smem);
  float* shb = smem + 12 * 512 * 4;  // 12*512 u2 = 24576 floats

  const int tid = threadIdx.x;
  const int JQ = tid >> 3;       // 0..63
  const int KH = tid & 7;        // 0..7
  const int jb = JQ * 4;         // base j of this thread's 4 columns
  const int kb = KH * 32;
  const int b0g = blockIdx.x * 2;

  // finalize ownership: item = KH -> j_off = KH&3, b = KH>>2
  const int j_fin = jb - (JQ & 0) + ((KH & 3) + ((tid >> 3) << 2));  // = JQ*4 + (KH&3)
  const int jf = JQ * 4 + (KH & 3);
  const int bf = KH >> 2;

  // ---- stage W regs: q = 0..4 (k = kb .. kb+19 in 4-float groups) ----
  ull wr[4][10];
  #pragma unroll
  for (int j = 0; j < 4; ++j) {
    const float4* wp =
        reinterpret_cast<const float4*>(W_hh + (jb + j) * HH + kb);
    #pragma unroll
    for (int q = 0; q < 5; ++q) {
      float4 f = __ldg(wp + q);
      wr[j][2 * q]     = pack2(f.x, f.y);
      wr[j][2 * q + 1] = pack2(f.z, f.w);
    }
  }
  // ---- stage W smem: q = 5..7 ----
  #pragma unroll
  for (int q = 5; q < 8; ++q) {
    #pragma unroll
    for (int j = 0; j < 4; ++j) {
      float4 f = __ldg(reinterpret_cast<const float4*>(
          W_hh + (jb + j) * HH + kb) + q);
      ulonglong2 v;
      v.x = pack2(f.x, f.y);
      v.y = pack2(f.z, f.w);
      sW[((q - 5) * 4 + j) * 512 + tid] = v;
    }
  }

  // ---- init h: h_old in reg, smem buffer 0 ----
  float h_old = hx[(b0g + bf) * HH + jf];
  shb[bf * 288 + (jf >> 5) * 36 + (jf & 31)] = h_old;
  __syncthreads();

  // xproj pointer for owned (b, j)
  const float* xqp = g_xproj + ((size_t)(b0g + bf) * TT) * HH + jf;
  float xq_cur = __ldg(xqp);

  for (int t = 0; t < TT; ++t) {
    const int rp = t & 1;
    float xq_nxt = 0.0f;
    if (t + 1 < TT) xq_nxt = __ldg(xqp + (size_t)(t + 1) * HH);

    const float* hbase = shb + rp * 576;
    const ulonglong2* hp0 =
        reinterpret_cast<const ulonglong2*>(hbase + KH * 36);
    const ulonglong2* hp1 =
        reinterpret_cast<const ulonglong2*>(hbase + 288 + KH * 36);

    ull a[8];
    #pragma unroll
    for (int i = 0; i < 8; ++i) a[i] = 0ull;

    #pragma unroll
    for (int q = 0; q < 8; ++q) {
      ulonglong2 v0 = hp0[q];
      ulonglong2 v1 = hp1[q];
      if (q < 5) {
        #pragma unroll
        for (int j = 0; j < 4; ++j) {
          a[j]     = ffma2(wr[j][2 * q],     v0.x, a[j]);
          a[j]     = ffma2(wr[j][2 * q + 1], v0.y, a[j]);
          a[4 + j] = ffma2(wr[j][2 * q],     v1.x, a[4 + j]);
          a[4 + j] = ffma2(wr[j][2 * q + 1], v1.y, a[4 + j]);
        }
      } else {
        #pragma unroll
        for (int j = 0; j < 4; ++j) {
          ulonglong2 wv = sW[((q - 5) * 4 + j) * 512 + tid];
          a[j]     = ffma2(wv.x, v0.x, a[j]);
          a[j]     = ffma2(wv.y, v0.y, a[j]);
          a[4 + j] = ffma2(wv.x, v1.x, a[4 + j]);
          a[4 + j] = ffma2(wv.y, v1.y, a[4 + j]);
        }
      }
    }

    // ---- warp-octet reduce-scatter over KH bits (items i: bit2=b, bits10=j)
    const bool s0 = (tid & 1), s1 = (tid & 2), s2 = (tid & 4);
    ull w4[4];
    #pragma unroll
    for (int r = 0; r < 4; ++r) {
      ull keep = s0 ? a[2 * r + 1] : a[2 * r];
      ull give = s0 ? a[2 * r]     : a[2 * r + 1];
      ull recv = __shfl_xor_sync(0xffffffffu, give, 1);
      w4[r] = add2(keep, recv);
    }
    ull w2[2];
    #pragma unroll
    for (int r = 0; r < 2; ++r) {
      ull keep = s1 ? w4[2 * r + 1] : w4[2 * r];
      ull give = s1 ? w4[2 * r]     : w4[2 * r + 1];
      ull recv = __shfl_xor_sync(0xffffffffu, give, 2);
      w2[r] = add2(keep, recv);
    }
    ull keep = s2 ? w2[1] : w2[0];
    ull give = s2 ? w2[0] : w2[1];
    ull recv = __shfl_xor_sync(0xffffffffu, give, 4);
    ull tot = add2(keep, recv);

    // ---- finalize owned (b, j) ----
    float p = hsum2(tot) + xq_cur;
    h_old = 0.8f * h_old + 0.2f * fmaxf(p, 0.0f);
    shb[(rp ^ 1) * 576 + bf * 288 + (jf >> 5) * 36 + (jf & 31)] = h_old;
    xq_cur = xq_nxt;
    __syncthreads();
  }

  // -------- epilogue (final h in parity-0 buffer) --------
  const float* hf0 = shb;        // batch b0
  const float* hf1 = shb + 288;  // batch b1
  float* out_actor  = out;                 // [B][A]
  float* out_critic = out + BB * AA;       // [B]
  float* out_hx     = out + BB * AA + BB;  // [B][H]

  if (tid < HH) {
    int pj = (tid >> 5) * 36 + (tid & 31);
    out_hx[b0g * HH + tid]       = hf0[pj];
    out_hx[(b0g + 1) * HH + tid] = hf1[pj];
  }

  const int wid = tid >> 5, lane = tid & 31;
  if (wid < AA) {
    float pa0 = 0.f, pa1 = 0.f;
    for (int jj = lane; jj < HH; jj += 32) {
      int pj = (jj >> 5) * 36 + (jj & 31);
      float wa = W_actor[wid * HH + jj];
      pa0 += wa * hf0[pj];
      pa1 += wa * hf1[pj];
    }
    #pragma unroll
    for (int off = 16; off; off >>= 1) {
      pa0 += __shfl_down_sync(0xffffffffu, pa0, off);
      pa1 += __shfl_down_sync(0xffffffffu, pa1, off);
    }
    if (lane == 0) {
      out_actor[b0g * AA + wid]       = pa0;
      out_actor[(b0g + 1) * AA + wid] = pa1;
    }
  }
  if (wid == 8) {
    float pc0 = 0.f, pc1 = 0.f;
    for (int jj = lane; jj < HH; jj += 32) {
      int pj = (jj >> 5) * 36 + (jj & 31);
      float wc = W_critic[jj];
      pc0 += wc * hf0[pj];
      pc1 += wc * hf1[pj];
    }
    #pragma unroll
    for (int off = 16; off; off >>= 1) {
      pc0 += __shfl_down_sync(0xffffffffu, pc0, off);
      pc1 += __shfl_down_sync(0xffffffffu, pc1, off);
    }
    if (lane == 0) {
      out_critic[b0g]     = pc0;
      out_critic[b0g + 1] = pc1;
    }
  }
}

// ---------------------------------------------------------------------------
extern "C" void kernel_launch(void* const* d_in, const int* in_sizes, int n_in,
                              void* d_out, int out_size) {
  const float* x        = (const float*)d_in[0];
  const float* hx       = (const float*)d_in[1];
  const float* W_ih     = (const float*)d_in[2];
  const float* W_hh     = (const float*)d_in[3];
  const float* W_actor  = (const float*)d_in[4];
  const float* W_critic = (const float*)d_in[5];
  float* out = (float*)d_out;

  // smem: W 12*512*16B = 98304B + h 2*2*288*4B = 4608B
  const int smem2 = 98304 + 4608;

  cudaFuncSetAttribute(recurrence_kernel,
                       cudaFuncAttributeMaxDynamicSharedMemorySize, smem2);

  xproj_kernel<<<(BB * TT) / 256, 512>>>(x, W_ih);
  recurrence_kernel<<<BB / 2, 512, smem2>>>(hx, W_hh, W_actor, W_critic, out);
}